// round 12
// baseline (speedup 1.0000x reference)
#include <cuda_runtime.h>
#include <stdint.h>
#include <math.h>

#define BATCH 32
#define CHAN  256
#define HH    56
#define WW    56
#define S     (HH*WW)        // 3136
#define S4    (S/4)          // 784
#define QSPLIT 4
#define CQ    (CHAN/QSPLIT)  // 64
#define RNUM  1568           // removed_num = round(3136*0.5)
#define RB    7              // 8-row slabs per batch

// scratch (no cudaMalloc allowed)
__device__ __align__(16) float        g_part_max[QSPLIT*BATCH*S];
__device__ __align__(16) float        g_part_sum[QSPLIT*BATCH*S];
__device__ __align__(16) unsigned int g_uvals[BATCH*S];
__device__ __align__(16) float        g_y[BATCH*S];

// ---------------------------------------------------------------------------
// Kernel 1: partial channel max/sum. 392 blocks x 256 threads, QSPLIT=4
// (measured identical to QSPLIT=8 pool: ~19.3us; halves partial traffic).
// ---------------------------------------------------------------------------
__global__ void pool_partial(const float* __restrict__ x) {
    int gid = blockIdx.x * blockDim.x + threadIdx.x;
    int q   = gid / (BATCH * S4);
    int rem = gid % (BATCH * S4);
    int b   = rem / S4;
    int s4  = rem % S4;

    const float4* p = reinterpret_cast<const float4*>(x)
                    + (size_t)(b * CHAN + q * CQ) * S4 + s4;

    float4 mx = make_float4(-INFINITY, -INFINITY, -INFINITY, -INFINITY);
    float4 sm = make_float4(0.f, 0.f, 0.f, 0.f);

    #pragma unroll 8
    for (int c = 0; c < CQ; ++c) {
        float4 v = __ldcs(p + (size_t)c * S4);   // read-once: stream past L2
        mx.x = fmaxf(mx.x, v.x); mx.y = fmaxf(mx.y, v.y);
        mx.z = fmaxf(mx.z, v.z); mx.w = fmaxf(mx.w, v.w);
        sm.x += v.x; sm.y += v.y; sm.z += v.z; sm.w += v.w;
    }

    int o = (q * BATCH + b) * S4 + s4;
    reinterpret_cast<float4*>(g_part_max)[o] = mx;
    reinterpret_cast<float4*>(g_part_sum)[o] = sm;
}

// ---------------------------------------------------------------------------
// Kernel 2: combine partials + 3x3 conv + sigmoid -> g_uvals. 224 blocks
// (BATCH*RB) x 448 threads; each block owns an 8-row slab + 1-row halo.
// Full-chip parallel; partials L2-hot.
// ---------------------------------------------------------------------------
__global__ void __launch_bounds__(448) conv_sig(const float* __restrict__ w) {
    __shared__ float pm[10 * WW];
    __shared__ float pa[10 * WW];
    __shared__ float ws[18];

    const int b  = blockIdx.x / RB;
    const int rb = blockIdx.x % RB;
    const int t  = threadIdx.x;
    const int row0 = rb * 8 - 1;            // global row of smem row 0

    if (t < 18) ws[t] = w[t];

    const float inv = 1.0f / (float)CHAN;
    for (int j = t; j < 10 * WW; j += 448) {
        int grow = row0 + j / WW;
        int col  = j % WW;
        float mx = 0.f, sm = 0.f;
        if (grow >= 0 && grow < HH) {
            int base = grow * WW + col;
            mx = -INFINITY;
            #pragma unroll
            for (int q = 0; q < QSPLIT; ++q) {
                int o = (q * BATCH + b) * S + base;
                mx = fmaxf(mx, g_part_max[o]);
                sm += g_part_sum[o];
            }
            sm *= inv;
        }
        pm[j] = mx;
        pa[j] = sm;
    }
    __syncthreads();

    const int ohl = t / WW;                 // 0..7 local row
    const int ow  = t % WW;
    const int oh  = rb * 8 + ohl;

    float acc = 0.f;
    #pragma unroll
    for (int ky = 0; ky < 3; ++ky) {
        int ih = oh + ky - 1;
        if (ih < 0 || ih >= HH) continue;
        int lr = ohl + ky;                  // smem row
        #pragma unroll
        for (int kx = 0; kx < 3; ++kx) {
            int iw = ow + kx - 1;
            if (iw < 0 || iw >= WW) continue;
            int ii = lr * WW + iw;
            acc = fmaf(pm[ii], ws[ky * 3 + kx], acc);
            acc = fmaf(pa[ii], ws[9 + ky * 3 + kx], acc);
        }
    }
    float y = 1.0f / (1.0f + expf(-acc));
    g_uvals[b * S + oh * WW + ow] = __float_as_uint(y);
}

// ---------------------------------------------------------------------------
// Kernel 3: per-batch exact radix select (rank RNUM-1) + masked write.
// One block per batch, 1024 threads. Loads 12.5KB L2-hot values; pass-0
// histogram fused into the load sweep. Warp-0 bin scan, 3 barriers/pass.
// ---------------------------------------------------------------------------
__global__ void __launch_bounds__(1024, 1) select_mask() {
    __shared__ unsigned int uvals[S];
    __shared__ int hist[256];
    __shared__ unsigned int s_prefix;
    __shared__ int s_r, s_less;
    __shared__ int tieIdx[256];
    __shared__ int tieCount;

    const int b = blockIdx.x;
    const int t = threadIdx.x;
    const int lane = t & 31;

    if (t < 256) hist[t] = 0;
    if (t == 0) { s_r = RNUM - 1; s_less = 0; s_prefix = 0u; tieCount = 0; }
    __syncthreads();

    // load + fused pass-0 histogram (high 8 bits)
    for (int i = t; i < S; i += 1024) {
        unsigned int u = g_uvals[b * S + i];
        uvals[i] = u;
        atomicAdd(&hist[u >> 24], 1);
    }
    __syncthreads();

    #pragma unroll
    for (int pass = 0; pass < 4; ++pass) {
        const int shift = 24 - 8 * pass;

        if (pass > 0) {
            const unsigned int pmask = 0xFFFFFFFFu << (32 - 8 * pass);
            const unsigned int pref  = s_prefix;
            for (int i = t; i < S; i += 1024) {
                unsigned int u = uvals[i];
                if ((u & pmask) == pref)
                    atomicAdd(&hist[(u >> shift) & 0xFF], 1);
            }
            __syncthreads();
        }

        if (t < 32) {                      // warp-0 bin scan + select
            int base = t * 8;
            int h0 = hist[base + 0], h1 = hist[base + 1];
            int h2 = hist[base + 2], h3 = hist[base + 3];
            int h4 = hist[base + 4], h5 = hist[base + 5];
            int h6 = hist[base + 6], h7 = hist[base + 7];
            int tot = h0 + h1 + h2 + h3 + h4 + h5 + h6 + h7;

            int ex = tot;                  // -> exclusive prefix of lane totals
            #pragma unroll
            for (int d = 1; d < 32; d <<= 1) {
                int n = __shfl_up_sync(0xFFFFFFFFu, ex, d);
                if (lane >= d) ex += n;
            }
            ex -= tot;

            int r = s_r;
            if (ex <= r && r < ex + tot) { // exactly one lane matches
                int cum = ex, bin = base;
                int hh[8] = {h0,h1,h2,h3,h4,h5,h6,h7};
                #pragma unroll
                for (int k = 0; k < 8; ++k) {
                    if (cum + hh[k] > r) { bin = base + k; break; }
                    cum += hh[k];
                }
                s_r      = r - cum;
                s_less  += cum;
                s_prefix = (pass == 0 ? 0u : s_prefix) | ((unsigned int)bin << shift);
            }
        }
        __syncthreads();

        if (pass < 3) {
            if (t < 256) hist[t] = 0;
            __syncthreads();
        }
    }

    const unsigned int T = s_prefix;
    const int zeroTies = RNUM - s_less;    // # ties (==T) to zero, ascending index

    // merged masked write + tie collection (single sweep)
    float* yb = g_y + b * S;
    for (int i = t; i < S; i += 1024) {
        unsigned int u = uvals[i];
        float v = __uint_as_float(u);
        if (u < T) v = 0.0f;
        else if (u == T) {
            int p = atomicAdd(&tieCount, 1);
            if (p < 256) tieIdx[p] = i;
        }
        yb[i] = v;                         // ties fixed below
    }
    __syncthreads();

    if (t == 0) {
        int tc = tieCount < 256 ? tieCount : 256;
        for (int i = 1; i < tc; ++i) {     // expected tc == 1
            int v2 = tieIdx[i], j = i - 1;
            while (j >= 0 && tieIdx[j] > v2) { tieIdx[j + 1] = tieIdx[j]; --j; }
            tieIdx[j + 1] = v2;
        }
        int z = zeroTies < tc ? zeroTies : tc;
        for (int j = 0; j < z; ++j) yb[tieIdx[j]] = 0.0f;
    }
}

// ---------------------------------------------------------------------------
// Kernel 4: broadcast masked map to all 256 channels.
// 1 float4 load -> 8 streaming (__stcs) stores; 1568 blocks x 512 threads.
// ---------------------------------------------------------------------------
__global__ void __launch_bounds__(512) bcast(float* __restrict__ out) {
    int gid  = blockIdx.x * 512 + threadIdx.x;    // 0 .. BATCH*32*S4-1
    int s4   = gid % S4;
    int rowg = gid / S4;                          // b*32 + cg
    int b    = rowg >> 5;
    int cg   = rowg & 31;

    float4 v = __ldg(reinterpret_cast<const float4*>(g_y) + b * S4 + s4);

    float4* p = reinterpret_cast<float4*>(out)
              + ((size_t)(b * CHAN + cg * 8)) * S4 + s4;
    #pragma unroll
    for (int k = 0; k < 8; ++k) {
        __stcs(p, v);                      // evict-first: don't churn L2
        p += S4;
    }
}

// ---------------------------------------------------------------------------
extern "C" void kernel_launch(void* const* d_in, const int* in_sizes, int n_in,
                              void* d_out, int out_size) {
    const float* x = (const float*)d_in[0];   // [32,256,56,56]
    const float* w = (const float*)d_in[1];   // [1,2,3,3]
    float* out = (float*)d_out;               // [32,256,56,56]

    pool_partial<<<(QSPLIT * BATCH * S4) / 256, 256>>>(x);   // 392 blocks
    conv_sig<<<BATCH * RB, 448>>>(w);                        // 224 blocks
    select_mask<<<BATCH, 1024>>>();                          // 32 blocks
    bcast<<<(BATCH * 32 * S4) / 512, 512>>>(out);            // 1568 blocks
}

// round 13
// speedup vs baseline: 1.0081x; 1.0081x over previous
#include <cuda_runtime.h>
#include <stdint.h>
#include <math.h>

#define BATCH 32
#define CHAN  256
#define HH    56
#define WW    56
#define S     (HH*WW)        // 3136
#define S4    (S/4)          // 784
#define QSPLIT 4
#define CQ    (CHAN/QSPLIT)  // 64
#define RNUM  1568           // removed_num = round(3136*0.5)

// scratch (no cudaMalloc allowed)
__device__ __align__(16) float g_part_max[QSPLIT*BATCH*S];
__device__ __align__(16) float g_part_sum[QSPLIT*BATCH*S];
__device__ __align__(16) float g_y[BATCH*S];

// ---------------------------------------------------------------------------
// Kernel 1: partial channel max/sum. QSPLIT=4 -> half the partial traffic of
// R11. 392 blocks x 512 threads = same 200K threads as the 784x256 shape.
// ---------------------------------------------------------------------------
__global__ void __launch_bounds__(512) pool_partial(const float* __restrict__ x) {
    int gid = blockIdx.x * blockDim.x + threadIdx.x;
    int q   = gid / (BATCH * S4);
    int rem = gid % (BATCH * S4);
    int b   = rem / S4;
    int s4  = rem % S4;

    const float4* p = reinterpret_cast<const float4*>(x)
                    + (size_t)(b * CHAN + q * CQ) * S4 + s4;

    float4 mx = make_float4(-INFINITY, -INFINITY, -INFINITY, -INFINITY);
    float4 sm = make_float4(0.f, 0.f, 0.f, 0.f);

    #pragma unroll 8
    for (int c = 0; c < CQ; ++c) {
        float4 v = __ldcs(p + (size_t)c * S4);   // read-once: stream past L2
        mx.x = fmaxf(mx.x, v.x); mx.y = fmaxf(mx.y, v.y);
        mx.z = fmaxf(mx.z, v.z); mx.w = fmaxf(mx.w, v.w);
        sm.x += v.x; sm.y += v.y; sm.z += v.z; sm.w += v.w;
    }

    int o = (q * BATCH + b) * S4 + s4;
    reinterpret_cast<float4*>(g_part_max)[o] = mx;
    reinterpret_cast<float4*>(g_part_sum)[o] = sm;
}

// ---------------------------------------------------------------------------
// Kernel 2 (fused middle): combine partials (200KB/batch from L2),
// conv+sigmoid with pass-0 histogram fused, exact radix select, masked write
// with merged tie collection. One block per batch, 1024 threads.
// ---------------------------------------------------------------------------
__global__ void __launch_bounds__(1024, 1) fused_mid(const float* __restrict__ w) {
    __shared__ float pm[S];
    __shared__ float pa[S];
    __shared__ unsigned int uvals[S];     // sigmoid bits; >0 so uint order == float order
    __shared__ int hist[256];
    __shared__ float ws[18];
    __shared__ unsigned int s_prefix;
    __shared__ int s_r, s_less;
    __shared__ int tieIdx[256];
    __shared__ int tieCount;

    const int b = blockIdx.x;
    const int t = threadIdx.x;
    const int lane = t & 31;

    if (t < 18) ws[t] = w[t];
    if (t < 256) hist[t] = 0;             // pre-clear for fused pass 0
    if (t == 0) { s_r = RNUM - 1; s_less = 0; s_prefix = 0u; tieCount = 0; }

    // --- combine QSPLIT partials -> pooled max/avg in smem (float4/thread) ---
    const float inv = 1.0f / (float)CHAN;
    if (t < S4) {
        float4 mx = make_float4(-INFINITY, -INFINITY, -INFINITY, -INFINITY);
        float4 sm = make_float4(0.f, 0.f, 0.f, 0.f);
        #pragma unroll
        for (int q = 0; q < QSPLIT; ++q) {
            int o = (q * BATCH + b) * S4 + t;
            float4 m = reinterpret_cast<const float4*>(g_part_max)[o];
            float4 s = reinterpret_cast<const float4*>(g_part_sum)[o];
            mx.x = fmaxf(mx.x, m.x); mx.y = fmaxf(mx.y, m.y);
            mx.z = fmaxf(mx.z, m.z); mx.w = fmaxf(mx.w, m.w);
            sm.x += s.x; sm.y += s.y; sm.z += s.z; sm.w += s.w;
        }
        sm.x *= inv; sm.y *= inv; sm.z *= inv; sm.w *= inv;
        reinterpret_cast<float4*>(pm)[t] = mx;
        reinterpret_cast<float4*>(pa)[t] = sm;
    }
    __syncthreads();

    // --- conv 3x3 (2ch->1ch, pad 1, cross-corr OIHW) + sigmoid + pass-0 hist ---
    for (int i = t; i < S; i += 1024) {
        int oh = i / WW, ow = i % WW;
        float acc = 0.f;
        #pragma unroll
        for (int ky = 0; ky < 3; ++ky) {
            int ih = oh + ky - 1;
            if (ih < 0 || ih >= HH) continue;
            #pragma unroll
            for (int kx = 0; kx < 3; ++kx) {
                int iw = ow + kx - 1;
                if (iw < 0 || iw >= WW) continue;
                int ii = ih * WW + iw;
                acc = fmaf(pm[ii], ws[ky * 3 + kx], acc);
                acc = fmaf(pa[ii], ws[9 + ky * 3 + kx], acc);
            }
        }
        unsigned int u = __float_as_uint(1.0f / (1.0f + expf(-acc)));
        uvals[i] = u;
        atomicAdd(&hist[u >> 24], 1);      // fused radix pass 0
    }
    __syncthreads();

    // --- 4-pass radix select (pass 0 histogram already built) ---
    #pragma unroll
    for (int pass = 0; pass < 4; ++pass) {
        const int shift = 24 - 8 * pass;

        if (pass > 0) {
            const unsigned int pmask = 0xFFFFFFFFu << (32 - 8 * pass);
            const unsigned int pref  = s_prefix;
            for (int i = t; i < S; i += 1024) {
                unsigned int u = uvals[i];
                if ((u & pmask) == pref)
                    atomicAdd(&hist[(u >> shift) & 0xFF], 1);
            }
            __syncthreads();
        }

        if (t < 32) {                      // warp-0 bin scan + select
            int base = t * 8;
            int h0 = hist[base + 0], h1 = hist[base + 1];
            int h2 = hist[base + 2], h3 = hist[base + 3];
            int h4 = hist[base + 4], h5 = hist[base + 5];
            int h6 = hist[base + 6], h7 = hist[base + 7];
            int tot = h0 + h1 + h2 + h3 + h4 + h5 + h6 + h7;

            int ex = tot;                  // -> exclusive prefix of lane totals
            #pragma unroll
            for (int d = 1; d < 32; d <<= 1) {
                int n = __shfl_up_sync(0xFFFFFFFFu, ex, d);
                if (lane >= d) ex += n;
            }
            ex -= tot;

            int r = s_r;
            if (ex <= r && r < ex + tot) { // exactly one lane matches
                int cum = ex, bin = base;
                int hh[8] = {h0,h1,h2,h3,h4,h5,h6,h7};
                #pragma unroll
                for (int k = 0; k < 8; ++k) {
                    if (cum + hh[k] > r) { bin = base + k; break; }
                    cum += hh[k];
                }
                s_r      = r - cum;
                s_less  += cum;
                s_prefix = (pass == 0 ? 0u : s_prefix) | ((unsigned int)bin << shift);
            }
        }
        __syncthreads();

        if (pass < 3) {                    // clear for next pass
            if (t < 256) hist[t] = 0;
            __syncthreads();
        }
    }

    const unsigned int T = s_prefix;
    const int zeroTies = RNUM - s_less;    // # ties (==T) to zero, ascending index

    // --- merged masked write + tie collection (single sweep) ---
    float* yb = g_y + b * S;
    for (int i = t; i < S; i += 1024) {
        unsigned int u = uvals[i];
        float v = __uint_as_float(u);
        if (u < T) v = 0.0f;
        else if (u == T) {
            int p = atomicAdd(&tieCount, 1);
            if (p < 256) tieIdx[p] = i;
        }
        yb[i] = v;                         // ties fixed below
    }
    __syncthreads();

    if (t == 0) {
        int tc = tieCount < 256 ? tieCount : 256;
        for (int i = 1; i < tc; ++i) {     // expected tc == 1
            int v2 = tieIdx[i], j = i - 1;
            while (j >= 0 && tieIdx[j] > v2) { tieIdx[j + 1] = tieIdx[j]; --j; }
            tieIdx[j + 1] = v2;
        }
        int z = zeroTies < tc ? zeroTies : tc;
        for (int j = 0; j < z; ++j) yb[tieIdx[j]] = 0.0f;
    }
}

// ---------------------------------------------------------------------------
// Kernel 3: broadcast masked map to all 256 channels. (Best measured: 16.0us)
// 1 float4 load -> 8 streaming (__stcs) stores; 1568 blocks x 512 threads.
// ---------------------------------------------------------------------------
__global__ void __launch_bounds__(512) bcast(float* __restrict__ out) {
    int gid  = blockIdx.x * 512 + threadIdx.x;    // 0 .. BATCH*32*S4-1
    int s4   = gid % S4;
    int rowg = gid / S4;                          // b*32 + cg
    int b    = rowg >> 5;
    int cg   = rowg & 31;

    float4 v = __ldg(reinterpret_cast<const float4*>(g_y) + b * S4 + s4);

    float4* p = reinterpret_cast<float4*>(out)
              + ((size_t)(b * CHAN + cg * 8)) * S4 + s4;
    #pragma unroll
    for (int k = 0; k < 8; ++k) {
        __stcs(p, v);                      // evict-first: don't churn L2
        p += S4;
    }
}

// ---------------------------------------------------------------------------
extern "C" void kernel_launch(void* const* d_in, const int* in_sizes, int n_in,
                              void* d_out, int out_size) {
    const float* x = (const float*)d_in[0];   // [32,256,56,56]
    const float* w = (const float*)d_in[1];   // [1,2,3,3]
    float* out = (float*)d_out;               // [32,256,56,56]

    pool_partial<<<(QSPLIT * BATCH * S4) / 512, 512>>>(x);   // 392 blocks x 512
    fused_mid<<<BATCH, 1024>>>(w);                           // 32 blocks
    bcast<<<(BATCH * 32 * S4) / 512, 512>>>(out);            // 1568 blocks
}